// round 3
// baseline (speedup 1.0000x reference)
#include <cuda_runtime.h>
#include <math.h>

#define NPIX 50176
#define CF   4224
#define NS   128
#define DH   1024
#define PPB  392      // NPIX / 128 pixels per histogram/scatter block
#define RC   4        // row-chunks per segment for segsum
#define ROWQ (CF / 4) // 1056 float4 per pixfeat row
#define SST  352      // segsum threads (11 warps); 352 * 3 = 1056 float4 = full row
#define CHUNKCAP 256  // smem idx cap per (chunk,segment): mean ~98, 2.6x headroom

// ---------------- scratch (static device memory only) ----------------------
__device__ int   g_hist[NS];
__device__ int   g_cls[NS * 3];
__device__ int   g_off[NS + 1];
__device__ int   g_bh[NS * NS];     // per-block per-segment counts
__device__ int   g_bbase[NS * NS];  // per-block per-segment write bases
__device__ int   g_perm[NPIX];
__device__ int   g_lab[NS];
__device__ float g_part[RC * NS * CF];  // segsum partials (8.65 MB)
__device__ float g_feat[NS * CF];
__device__ float g_G[NS * NS];
__device__ float g_h1[NS * DH];
__device__ float g_h2[NS * DH];
__device__ float g_h3[NS * 32];

// ---------------- K0: zero atomic accumulators ------------------------------
__global__ void k_zero() {
    int i = blockIdx.x * blockDim.x + threadIdx.x;
    if (i < NS * DH) { g_h1[i] = 0.f; g_h2[i] = 0.f; }
    if (i < NS * NS) g_G[i] = 0.f;
    if (i < NS * 3)  g_cls[i] = 0;
}

// ---------------- K1: per-block segment histograms + class counts ----------
__global__ void k_hist(const int* __restrict__ sp, const int* __restrict__ y) {
    __shared__ int sh[NS];
    __shared__ int sc[NS * 3];
    for (int i = threadIdx.x; i < NS; i += 256) sh[i] = 0;
    for (int i = threadIdx.x; i < NS * 3; i += 256) sc[i] = 0;
    __syncthreads();
    int b = blockIdx.x;
    int base = b * PPB;
    for (int t = threadIdx.x; t < PPB; t += 256) {
        int i = base + t;
        int s = sp[i];
        atomicAdd(&sh[s], 1);
        atomicAdd(&sc[s * 3 + y[i]], 1);
    }
    __syncthreads();
    for (int i = threadIdx.x; i < NS; i += 256) g_bh[b * NS + i] = sh[i];
    for (int i = threadIdx.x; i < NS * 3; i += 256)
        if (sc[i]) atomicAdd(&g_cls[i], sc[i]);
}

// ---------------- K2: offsets, per-block bases, exact label logic ----------
__global__ void k_meta() {
    int s = threadIdx.x;  // 128 threads
    __shared__ int tot[NS];
    int acc = 0;
    #pragma unroll 4
    for (int b = 0; b < NS; b++) acc += g_bh[b * NS + s];
    tot[s] = acc;
    g_hist[s] = acc;
    __syncthreads();
    if (s == 0) {
        int a = 0;
        for (int i = 0; i < NS; i++) { g_off[i] = a; a += tot[i]; }
        g_off[NS] = a;
    }
    __syncthreads();
    int base = g_off[s];
    #pragma unroll 4
    for (int b = 0; b < NS; b++) {
        g_bbase[b * NS + s] = base;
        base += g_bh[b * NS + s];
    }
    int c0 = g_cls[s * 3 + 0];
    int c1 = g_cls[s * 3 + 1];
    int c2 = g_cls[s * 3 + 2];
    int lab = (c1 > c0) ? ((c2 > c1) ? 2 : 1) : ((c2 > c0) ? 2 : 0);
    if (lab == 0) {
        int cnt = g_hist[s];
        lab = (c2 > (cnt >> 1)) ? 2 : ((c1 >= 1) ? 1 : 0);
    }
    g_lab[s] = lab;
}

// ---------------- K3: scatter via smem atomics against precomputed bases ---
__global__ void k_scatter(const int* __restrict__ sp) {
    __shared__ int cur[NS];
    int b = blockIdx.x;
    for (int i = threadIdx.x; i < NS; i += 256) cur[i] = g_bbase[b * NS + i];
    __syncthreads();
    int base = b * PPB;
    for (int t = threadIdx.x; t < PPB; t += 256) {
        int i = base + t;
        int s = sp[i];
        int p = atomicAdd(&cur[s], 1);
        g_perm[p] = i;
    }
}

// ---------------- K4: segment partial sums, FULL-ROW sequential reads ------
// grid = (RC row-chunks, NS segments) = 512 blocks, 352 threads.
// Each iteration streams one complete 16.9 KB pixfeat row contiguously:
// thread t loads float4 at t, t+352, t+704. 2-row unroll -> 6 LDG.128 in
// flight per thread. Partials to g_part (written fully; no init needed).
__global__ void __launch_bounds__(SST) k_segsum(const float* __restrict__ pix) {
    int c = blockIdx.x;   // row chunk
    int s = blockIdx.y;   // segment
    int t = threadIdx.x;
    int beg = g_off[s], end = g_off[s + 1];
    int n = end - beg;
    int r0 = beg + (n * c) / RC;
    int r1 = beg + (n * (c + 1)) / RC;
    int cnt = r1 - r0;

    __shared__ int sidx[CHUNKCAP];
    int cap = cnt < CHUNKCAP ? cnt : CHUNKCAP;
    for (int i = t; i < cap; i += SST) sidx[i] = g_perm[r0 + i];
    __syncthreads();

    const float4* __restrict__ p4 = (const float4*)pix;
    float4 a0 = make_float4(0.f, 0.f, 0.f, 0.f);
    float4 a1 = make_float4(0.f, 0.f, 0.f, 0.f);
    float4 a2 = make_float4(0.f, 0.f, 0.f, 0.f);

    int r = 0;
    for (; r + 1 < cap; r += 2) {
        size_t b0 = (size_t)sidx[r] * ROWQ;
        size_t b1 = (size_t)sidx[r + 1] * ROWQ;
        float4 v0 = __ldg(p4 + b0 + t);
        float4 v1 = __ldg(p4 + b0 + t + SST);
        float4 v2 = __ldg(p4 + b0 + t + 2 * SST);
        float4 w0 = __ldg(p4 + b1 + t);
        float4 w1 = __ldg(p4 + b1 + t + SST);
        float4 w2 = __ldg(p4 + b1 + t + 2 * SST);
        a0.x += v0.x; a0.y += v0.y; a0.z += v0.z; a0.w += v0.w;
        a1.x += v1.x; a1.y += v1.y; a1.z += v1.z; a1.w += v1.w;
        a2.x += v2.x; a2.y += v2.y; a2.z += v2.z; a2.w += v2.w;
        a0.x += w0.x; a0.y += w0.y; a0.z += w0.z; a0.w += w0.w;
        a1.x += w1.x; a1.y += w1.y; a1.z += w1.z; a1.w += w1.w;
        a2.x += w2.x; a2.y += w2.y; a2.z += w2.z; a2.w += w2.w;
    }
    if (r < cap) {
        size_t b0 = (size_t)sidx[r] * ROWQ;
        float4 v0 = __ldg(p4 + b0 + t);
        float4 v1 = __ldg(p4 + b0 + t + SST);
        float4 v2 = __ldg(p4 + b0 + t + 2 * SST);
        a0.x += v0.x; a0.y += v0.y; a0.z += v0.z; a0.w += v0.w;
        a1.x += v1.x; a1.y += v1.y; a1.z += v1.z; a1.w += v1.w;
        a2.x += v2.x; a2.y += v2.y; a2.z += v2.z; a2.w += v2.w;
    }
    // fallback for chunks larger than CHUNKCAP (statistically impossible)
    for (int r2 = CHUNKCAP; r2 < cnt; r2++) {
        size_t b0 = (size_t)g_perm[r0 + r2] * ROWQ;
        float4 v0 = __ldg(p4 + b0 + t);
        float4 v1 = __ldg(p4 + b0 + t + SST);
        float4 v2 = __ldg(p4 + b0 + t + 2 * SST);
        a0.x += v0.x; a0.y += v0.y; a0.z += v0.z; a0.w += v0.w;
        a1.x += v1.x; a1.y += v1.y; a1.z += v1.z; a1.w += v1.w;
        a2.x += v2.x; a2.y += v2.y; a2.z += v2.z; a2.w += v2.w;
    }

    float4* __restrict__ out4 = (float4*)&g_part[(c * NS + s) * CF];
    out4[t]           = a0;
    out4[t + SST]     = a1;
    out4[t + 2 * SST] = a2;
}

// ---------------- K4b: combine partials + divide by count -------------------
__global__ void k_combine() {
    int i = blockIdx.x * blockDim.x + threadIdx.x;  // NS*CF/4 = 135168 float4
    if (i >= NS * ROWQ) return;
    const float4* __restrict__ p4 = (const float4*)g_part;
    float4 a = p4[i];
    #pragma unroll
    for (int c = 1; c < RC; c++) {
        float4 v = p4[c * NS * ROWQ + i];
        a.x += v.x; a.y += v.y; a.z += v.z; a.w += v.w;
    }
    int s = i / ROWQ;
    float cn = (float)max(g_hist[s], 1);
    a.x /= cn; a.y /= cn; a.z /= cn; a.w /= cn;
    ((float4*)g_feat)[i] = a;
}

// ---------------- K5: Gram matrix G = feat @ feat^T (split-K, 66 blocks) ---
__global__ void k_gram() {
    __shared__ float As[64][129];
    int kc  = blockIdx.x;
    int tid = threadIdx.x;
    {
        int k  = tid & 63;
        int io = tid >> 6;
        #pragma unroll 8
        for (int p = 0; p < 32; p++) {
            int i = p * 4 + io;
            As[k][i] = g_feat[i * CF + kc * 64 + k];
        }
    }
    __syncthreads();
    int tx = tid & 15, ty = tid >> 4;
    float acc[8][8];
    #pragma unroll
    for (int m = 0; m < 8; m++)
        #pragma unroll
        for (int n = 0; n < 8; n++) acc[m][n] = 0.f;

    for (int kk = 0; kk < 64; kk++) {
        float a[8], b[8];
        #pragma unroll
        for (int m = 0; m < 8; m++) a[m] = As[kk][ty * 8 + m];
        #pragma unroll
        for (int n = 0; n < 8; n++) b[n] = As[kk][tx * 8 + n];
        #pragma unroll
        for (int m = 0; m < 8; m++)
            #pragma unroll
            for (int n = 0; n < 8; n++) acc[m][n] += a[m] * b[n];
    }
    #pragma unroll
    for (int m = 0; m < 8; m++)
        #pragma unroll
        for (int n = 0; n < 8; n++)
            atomicAdd(&g_G[(ty * 8 + m) * NS + tx * 8 + n], acc[m][n]);
}

// ---------------- K6: affinity-based label propagation ----------------------
__global__ void k_labels(float* __restrict__ out_lab) {
    __shared__ float nrm[NS];
    __shared__ int   labsh[NS];
    int i = threadIdx.x;
    labsh[i] = g_lab[i];
    nrm[i] = rsqrtf(g_G[i * NS + i]);
    __syncthreads();
    float maxv = -__int_as_float(0x7f800000);
    int best = 0;
    float ni = nrm[i];
    for (int j = 0; j < NS; j++) {
        if (labsh[j] != 0) {
            float a = g_G[i * NS + j] * ni * nrm[j];
            if (a > maxv) { maxv = a; best = j; }
        }
    }
    int lab = labsh[i];
    if (lab == 0 && maxv > 0.8f) lab = labsh[best];
    out_lab[i] = (float)lab;
}

// ---------------- K7/K8: MLP GEMMs (split-K tiled fp32, atomic combine) ----
template <int L>
__global__ void k_mlp_gemm(const float* __restrict__ B,
                           const float* __restrict__ bias) {
    const float* __restrict__ A = (L == 1) ? g_feat : g_h1;
    float* C = (L == 1) ? g_h1 : g_h2;
    const int K = (L == 1) ? CF : DH;
    const int N = DH;
    const int KCHUNK = 128;

    __shared__ float As[16][132];
    __shared__ float Bs[16][68];
    int tid = threadIdx.x;
    int tx = tid & 15, ty = tid >> 4;
    int ntile = blockIdx.x;
    int k0 = blockIdx.y * KCHUNK;

    float acc[8][4];
    #pragma unroll
    for (int m = 0; m < 8; m++)
        #pragma unroll
        for (int n = 0; n < 4; n++) acc[m][n] = 0.f;

    for (int kt = 0; kt < KCHUNK; kt += 16) {
        #pragma unroll
        for (int p = 0; p < 8; p++) {
            int r = ty + p * 16;
            int kg = k0 + kt + tx;
            float v = A[r * K + kg];
            if (L == 2) v = fmaxf(v + bias[kg], 0.f);
            As[tx][r] = v;
        }
        #pragma unroll
        for (int p = 0; p < 4; p++) {
            int k = p * 4 + (tid >> 6);
            int n = tid & 63;
            Bs[k][n] = B[(k0 + kt + k) * N + ntile * 64 + n];
        }
        __syncthreads();
        #pragma unroll
        for (int kk = 0; kk < 16; kk++) {
            float a[8], b[4];
            #pragma unroll
            for (int m = 0; m < 8; m++) a[m] = As[kk][ty * 8 + m];
            #pragma unroll
            for (int n = 0; n < 4; n++) b[n] = Bs[kk][tx * 4 + n];
            #pragma unroll
            for (int m = 0; m < 8; m++)
                #pragma unroll
                for (int n = 0; n < 4; n++) acc[m][n] += a[m] * b[n];
        }
        __syncthreads();
    }
    #pragma unroll
    for (int m = 0; m < 8; m++) {
        int r = ty * 8 + m;
        #pragma unroll
        for (int n = 0; n < 4; n++)
            atomicAdd(&C[r * N + ntile * 64 + tx * 4 + n], acc[m][n]);
    }
}

// ---------------- K9: h3 = relu(h2+b2) @ w3  (128x32, K=1024) --------------
__global__ void k_gemm3(const float* __restrict__ b2,
                        const float* __restrict__ w3) {
    int idx = blockIdx.x * blockDim.x + threadIdx.x;
    int i = idx >> 5, j = idx & 31;
    const float* __restrict__ h2r = g_h2 + i * DH;
    float acc = 0.f;
    #pragma unroll 8
    for (int k = 0; k < DH; k++)
        acc += fmaxf(h2r[k] + b2[k], 0.f) * w3[k * 32 + j];
    g_h3[idx] = acc;
}

// ---------------- K10: classifier head + softmax ----------------------------
__global__ void k_head(const float* __restrict__ b3,
                       const float* __restrict__ wc,
                       const float* __restrict__ bc,
                       float* __restrict__ out_probs) {
    int i = threadIdx.x;
    float l0 = bc[0], l1 = bc[1];
    #pragma unroll
    for (int k = 0; k < 32; k++) {
        float h = fmaxf(g_h3[i * 32 + k] + b3[k], 0.f);
        l0 += h * wc[k * 2 + 0];
        l1 += h * wc[k * 2 + 1];
    }
    float m = fmaxf(l0, l1);
    float e0 = expf(l0 - m), e1 = expf(l1 - m);
    float s = e0 + e1;
    out_probs[i * 2 + 0] = e0 / s;
    out_probs[i * 2 + 1] = e1 / s;
}

// ---------------- launch ----------------------------------------------------
extern "C" void kernel_launch(void* const* d_in, const int* in_sizes, int n_in,
                              void* d_out, int out_size) {
    const float* pixfeat = (const float*)d_in[0];
    const float* w1 = (const float*)d_in[1];
    const float* b1 = (const float*)d_in[2];
    const float* w2 = (const float*)d_in[3];
    const float* b2 = (const float*)d_in[4];
    const float* w3 = (const float*)d_in[5];
    const float* b3 = (const float*)d_in[6];
    const float* wc = (const float*)d_in[7];
    const float* bc = (const float*)d_in[8];
    const int*   sp = (const int*)d_in[9];
    const int*   yy = (const int*)d_in[10];
    float* out = (float*)d_out;  // [0,256): probs, [256,384): lab

    k_zero<<<512, 256>>>();
    k_hist<<<128, 256>>>(sp, yy);
    k_meta<<<1, 128>>>();
    k_scatter<<<128, 256>>>(sp);
    k_segsum<<<dim3(RC, NS), SST>>>(pixfeat);
    k_combine<<<(NS * ROWQ + 255) / 256, 256>>>();
    k_gram<<<66, 256>>>();
    k_labels<<<1, 128>>>(out + 256);
    k_mlp_gemm<1><<<dim3(16, 33), 256>>>(w1, nullptr);
    k_mlp_gemm<2><<<dim3(16, 8), 256>>>(w2, b1);
    k_gemm3<<<32, 128>>>(b2, w3);
    k_head<<<1, 128>>>(b3, wc, bc, out);
}

// round 4
// speedup vs baseline: 1.2235x; 1.2235x over previous
#include <cuda_runtime.h>
#include <math.h>

#define NPIX 50176
#define CF   4224
#define NS   128
#define DH   1024
#define PPB  392      // NPIX / 128 pixels per histogram/scatter block
#define ROWQ (CF / 4) // 1056 float4 per pixfeat row
#define SEGCAP 768    // smem idx cap per segment (mean 392, 12+ sigma headroom)

// ---------------- scratch (static device memory only) ----------------------
__device__ int   g_hist[NS];
__device__ int   g_off[NS + 1];
__device__ int   g_bh[NS * NS];        // per-block per-segment counts
__device__ int   g_bcls[NS * NS * 3];  // per-block per-segment class counts
__device__ int   g_bbase[NS * NS];     // per-block per-segment write bases
__device__ int   g_perm[NPIX];
__device__ int   g_lab[NS];
__device__ float g_feat[NS * CF];
__device__ float g_G[NS * NS];
__device__ float g_h1[NS * DH];
__device__ float g_h2[NS * DH];
__device__ float g_h3[NS * 32];

// ---------------- K1: per-block histograms + class counts (no glob atomics)-
__global__ void k_hist(const int* __restrict__ sp, const int* __restrict__ y) {
    __shared__ int sh[NS];
    __shared__ int sc[NS * 3];
    for (int i = threadIdx.x; i < NS; i += 256) sh[i] = 0;
    for (int i = threadIdx.x; i < NS * 3; i += 256) sc[i] = 0;
    __syncthreads();
    int b = blockIdx.x;
    int base = b * PPB;
    for (int t = threadIdx.x; t < PPB; t += 256) {
        int i = base + t;
        int s = sp[i];
        atomicAdd(&sh[s], 1);
        atomicAdd(&sc[s * 3 + y[i]], 1);
    }
    __syncthreads();
    for (int i = threadIdx.x; i < NS; i += 256) g_bh[b * NS + i] = sh[i];
    for (int i = threadIdx.x; i < NS * 3; i += 256) g_bcls[b * NS * 3 + i] = sc[i];
}

// ---------------- K2: offsets, per-block bases, exact label logic ----------
__global__ void k_meta() {
    int s = threadIdx.x;  // 128 threads
    __shared__ int tot[NS];
    int acc = 0, c0 = 0, c1 = 0, c2 = 0;
    for (int b = 0; b < NS; b++) {
        acc += g_bh[b * NS + s];
        c0 += g_bcls[b * NS * 3 + s * 3 + 0];
        c1 += g_bcls[b * NS * 3 + s * 3 + 1];
        c2 += g_bcls[b * NS * 3 + s * 3 + 2];
    }
    tot[s] = acc;
    g_hist[s] = acc;
    __syncthreads();
    if (s == 0) {
        int a = 0;
        for (int i = 0; i < NS; i++) { g_off[i] = a; a += tot[i]; }
        g_off[NS] = a;
    }
    __syncthreads();
    int base = g_off[s];
    #pragma unroll 4
    for (int b = 0; b < NS; b++) {
        g_bbase[b * NS + s] = base;
        base += g_bh[b * NS + s];
    }
    int lab = (c1 > c0) ? ((c2 > c1) ? 2 : 1) : ((c2 > c0) ? 2 : 0);
    if (lab == 0) lab = (c2 > (acc >> 1)) ? 2 : ((c1 >= 1) ? 1 : 0);
    g_lab[s] = lab;
}

// ---------------- K3: scatter via smem atomics against precomputed bases ---
__global__ void k_scatter(const int* __restrict__ sp) {
    __shared__ int cur[NS];
    int b = blockIdx.x;
    for (int i = threadIdx.x; i < NS; i += 256) cur[i] = g_bbase[b * NS + i];
    __syncthreads();
    int base = b * PPB;
    for (int t = threadIdx.x; t < PPB; t += 256) {
        int i = base + t;
        int s = sp[i];
        int p = atomicAdd(&cur[s], 1);
        g_perm[p] = i;
    }
}

// ---------------- K4: segment mean (4th launch -> lands in ncu window) -----
// grid = (33 col-tiles, 128 segments), 256 threads (8 warps x 32 lanes).
// 8 independent LDG.128 per thread per iter (4KB/warp in flight), __ldcs
// streaming hint. Indices staged in smem.
__global__ void __launch_bounds__(256) k_segsum(const float* __restrict__ pix) {
    int ct = blockIdx.x;
    int s  = blockIdx.y;
    int tx = threadIdx.x & 31;
    int ty = threadIdx.x >> 5;
    int beg = g_off[s], end = g_off[s + 1];
    int n = end - beg;

    __shared__ int sidx[SEGCAP];
    int cap = n < SEGCAP ? n : SEGCAP;
    for (int i = threadIdx.x; i < cap; i += 256) sidx[i] = g_perm[beg + i];
    __syncthreads();

    const float4* __restrict__ p4 = (const float4*)pix;
    int colq = ct * 32 + tx;

    float4 A0 = make_float4(0.f, 0.f, 0.f, 0.f);
    float4 A1 = make_float4(0.f, 0.f, 0.f, 0.f);
    float4 A2 = make_float4(0.f, 0.f, 0.f, 0.f);
    float4 A3 = make_float4(0.f, 0.f, 0.f, 0.f);

    int r = ty;
    for (; r + 56 < cap; r += 64) {
        float4 v0 = __ldcs(p4 + (size_t)sidx[r]      * ROWQ + colq);
        float4 v1 = __ldcs(p4 + (size_t)sidx[r +  8] * ROWQ + colq);
        float4 v2 = __ldcs(p4 + (size_t)sidx[r + 16] * ROWQ + colq);
        float4 v3 = __ldcs(p4 + (size_t)sidx[r + 24] * ROWQ + colq);
        float4 v4 = __ldcs(p4 + (size_t)sidx[r + 32] * ROWQ + colq);
        float4 v5 = __ldcs(p4 + (size_t)sidx[r + 40] * ROWQ + colq);
        float4 v6 = __ldcs(p4 + (size_t)sidx[r + 48] * ROWQ + colq);
        float4 v7 = __ldcs(p4 + (size_t)sidx[r + 56] * ROWQ + colq);
        A0.x += v0.x; A0.y += v0.y; A0.z += v0.z; A0.w += v0.w;
        A1.x += v1.x; A1.y += v1.y; A1.z += v1.z; A1.w += v1.w;
        A2.x += v2.x; A2.y += v2.y; A2.z += v2.z; A2.w += v2.w;
        A3.x += v3.x; A3.y += v3.y; A3.z += v3.z; A3.w += v3.w;
        A0.x += v4.x; A0.y += v4.y; A0.z += v4.z; A0.w += v4.w;
        A1.x += v5.x; A1.y += v5.y; A1.z += v5.z; A1.w += v5.w;
        A2.x += v6.x; A2.y += v6.y; A2.z += v6.z; A2.w += v6.w;
        A3.x += v7.x; A3.y += v7.y; A3.z += v7.z; A3.w += v7.w;
    }
    for (; r < cap; r += 8) {
        float4 v0 = __ldcs(p4 + (size_t)sidx[r] * ROWQ + colq);
        A0.x += v0.x; A0.y += v0.y; A0.z += v0.z; A0.w += v0.w;
    }
    for (int r2 = SEGCAP + ty; r2 < n; r2 += 8) {  // statistically impossible
        float4 v0 = __ldcs(p4 + (size_t)g_perm[beg + r2] * ROWQ + colq);
        A0.x += v0.x; A0.y += v0.y; A0.z += v0.z; A0.w += v0.w;
    }
    A0.x += A1.x + A2.x + A3.x;
    A0.y += A1.y + A2.y + A3.y;
    A0.z += A1.z + A2.z + A3.z;
    A0.w += A1.w + A2.w + A3.w;

    __shared__ float4 red[8][32];
    red[ty][tx] = A0;
    __syncthreads();
    if (ty == 0) {
        float4 t = red[0][tx];
        #pragma unroll
        for (int w = 1; w < 8; w++) {
            t.x += red[w][tx].x; t.y += red[w][tx].y;
            t.z += red[w][tx].z; t.w += red[w][tx].w;
        }
        float c = (float)max(n, 1);
        t.x /= c; t.y /= c; t.z /= c; t.w /= c;
        *(float4*)&g_feat[s * CF + colq * 4] = t;
    }
}

// ---------------- K0: zero atomic accumulators (only needed before gemms) --
__global__ void k_zero() {
    int i = blockIdx.x * blockDim.x + threadIdx.x;
    if (i < NS * DH) { g_h1[i] = 0.f; g_h2[i] = 0.f; }
    if (i < NS * NS) g_G[i] = 0.f;
}

// ---------------- K5: Gram matrix G = feat @ feat^T (split-K, 66 blocks) ---
__global__ void k_gram() {
    __shared__ float As[64][129];
    int kc  = blockIdx.x;
    int tid = threadIdx.x;
    {
        int k  = tid & 63;
        int io = tid >> 6;
        #pragma unroll 8
        for (int p = 0; p < 32; p++) {
            int i = p * 4 + io;
            As[k][i] = g_feat[i * CF + kc * 64 + k];
        }
    }
    __syncthreads();
    int tx = tid & 15, ty = tid >> 4;
    float acc[8][8];
    #pragma unroll
    for (int m = 0; m < 8; m++)
        #pragma unroll
        for (int n = 0; n < 8; n++) acc[m][n] = 0.f;

    for (int kk = 0; kk < 64; kk++) {
        float a[8], b[8];
        #pragma unroll
        for (int m = 0; m < 8; m++) a[m] = As[kk][ty * 8 + m];
        #pragma unroll
        for (int n = 0; n < 8; n++) b[n] = As[kk][tx * 8 + n];
        #pragma unroll
        for (int m = 0; m < 8; m++)
            #pragma unroll
            for (int n = 0; n < 8; n++) acc[m][n] += a[m] * b[n];
    }
    #pragma unroll
    for (int m = 0; m < 8; m++)
        #pragma unroll
        for (int n = 0; n < 8; n++)
            atomicAdd(&g_G[(ty * 8 + m) * NS + tx * 8 + n], acc[m][n]);
}

// ---------------- K6: affinity-based label propagation ----------------------
__global__ void k_labels(float* __restrict__ out_lab) {
    __shared__ float nrm[NS];
    __shared__ int   labsh[NS];
    int i = threadIdx.x;
    labsh[i] = g_lab[i];
    nrm[i] = rsqrtf(g_G[i * NS + i]);
    __syncthreads();
    float maxv = -__int_as_float(0x7f800000);
    int best = 0;
    float ni = nrm[i];
    for (int j = 0; j < NS; j++) {
        if (labsh[j] != 0) {
            float a = g_G[i * NS + j] * ni * nrm[j];
            if (a > maxv) { maxv = a; best = j; }
        }
    }
    int lab = labsh[i];
    if (lab == 0 && maxv > 0.8f) lab = labsh[best];
    out_lab[i] = (float)lab;
}

// ---------------- K7/K8: MLP GEMMs (split-K tiled fp32, atomic combine) ----
template <int L>
__global__ void k_mlp_gemm(const float* __restrict__ B,
                           const float* __restrict__ bias) {
    const float* __restrict__ A = (L == 1) ? g_feat : g_h1;
    float* C = (L == 1) ? g_h1 : g_h2;
    const int K = (L == 1) ? CF : DH;
    const int N = DH;
    const int KCHUNK = 128;

    __shared__ float As[16][132];
    __shared__ float Bs[16][68];
    int tid = threadIdx.x;
    int tx = tid & 15, ty = tid >> 4;
    int ntile = blockIdx.x;
    int k0 = blockIdx.y * KCHUNK;

    float acc[8][4];
    #pragma unroll
    for (int m = 0; m < 8; m++)
        #pragma unroll
        for (int n = 0; n < 4; n++) acc[m][n] = 0.f;

    for (int kt = 0; kt < KCHUNK; kt += 16) {
        #pragma unroll
        for (int p = 0; p < 8; p++) {
            int r = ty + p * 16;
            int kg = k0 + kt + tx;
            float v = A[r * K + kg];
            if (L == 2) v = fmaxf(v + bias[kg], 0.f);
            As[tx][r] = v;
        }
        #pragma unroll
        for (int p = 0; p < 4; p++) {
            int k = p * 4 + (tid >> 6);
            int n = tid & 63;
            Bs[k][n] = B[(k0 + kt + k) * N + ntile * 64 + n];
        }
        __syncthreads();
        #pragma unroll
        for (int kk = 0; kk < 16; kk++) {
            float a[8], b[4];
            #pragma unroll
            for (int m = 0; m < 8; m++) a[m] = As[kk][ty * 8 + m];
            #pragma unroll
            for (int n = 0; n < 4; n++) b[n] = Bs[kk][tx * 4 + n];
            #pragma unroll
            for (int m = 0; m < 8; m++)
                #pragma unroll
                for (int n = 0; n < 4; n++) acc[m][n] += a[m] * b[n];
        }
        __syncthreads();
    }
    #pragma unroll
    for (int m = 0; m < 8; m++) {
        int r = ty * 8 + m;
        #pragma unroll
        for (int n = 0; n < 4; n++)
            atomicAdd(&C[r * N + ntile * 64 + tx * 4 + n], acc[m][n]);
    }
}

// ---------------- K9: h3 = relu(h2+b2) @ w3  (128x32, K=1024) --------------
__global__ void k_gemm3(const float* __restrict__ b2,
                        const float* __restrict__ w3) {
    int idx = blockIdx.x * blockDim.x + threadIdx.x;
    int i = idx >> 5, j = idx & 31;
    const float* __restrict__ h2r = g_h2 + i * DH;
    float acc = 0.f;
    #pragma unroll 8
    for (int k = 0; k < DH; k++)
        acc += fmaxf(h2r[k] + b2[k], 0.f) * w3[k * 32 + j];
    g_h3[idx] = acc;
}

// ---------------- K10: classifier head + softmax ----------------------------
__global__ void k_head(const float* __restrict__ b3,
                       const float* __restrict__ wc,
                       const float* __restrict__ bc,
                       float* __restrict__ out_probs) {
    int i = threadIdx.x;
    float l0 = bc[0], l1 = bc[1];
    #pragma unroll
    for (int k = 0; k < 32; k++) {
        float h = fmaxf(g_h3[i * 32 + k] + b3[k], 0.f);
        l0 += h * wc[k * 2 + 0];
        l1 += h * wc[k * 2 + 1];
    }
    float m = fmaxf(l0, l1);
    float e0 = expf(l0 - m), e1 = expf(l1 - m);
    float s = e0 + e1;
    out_probs[i * 2 + 0] = e0 / s;
    out_probs[i * 2 + 1] = e1 / s;
}

// ---------------- launch ----------------------------------------------------
extern "C" void kernel_launch(void* const* d_in, const int* in_sizes, int n_in,
                              void* d_out, int out_size) {
    const float* pixfeat = (const float*)d_in[0];
    const float* w1 = (const float*)d_in[1];
    const float* b1 = (const float*)d_in[2];
    const float* w2 = (const float*)d_in[3];
    const float* b2 = (const float*)d_in[4];
    const float* w3 = (const float*)d_in[5];
    const float* b3 = (const float*)d_in[6];
    const float* wc = (const float*)d_in[7];
    const float* bc = (const float*)d_in[8];
    const int*   sp = (const int*)d_in[9];
    const int*   yy = (const int*)d_in[10];
    float* out = (float*)d_out;  // [0,256): probs, [256,384): lab

    k_hist<<<128, 256>>>(sp, yy);        // 1
    k_meta<<<1, 128>>>();                // 2
    k_scatter<<<128, 256>>>(sp);         // 3
    k_segsum<<<dim3(33, NS), 256>>>(pixfeat);  // 4  <- profiled slot
    k_zero<<<512, 256>>>();              // 5
    k_gram<<<66, 256>>>();               // 6
    k_labels<<<1, 128>>>(out + 256);     // 7
    k_mlp_gemm<1><<<dim3(16, 33), 256>>>(w1, nullptr);
    k_mlp_gemm<2><<<dim3(16, 8), 256>>>(w2, b1);
    k_gemm3<<<32, 128>>>(b2, w3);
    k_head<<<1, 128>>>(b3, wc, bc, out);
}

// round 5
// speedup vs baseline: 1.6984x; 1.3882x over previous
#include <cuda_runtime.h>
#include <math.h>

#define NPIX 50176
#define CF   4224
#define NS   128
#define DH   1024
#define PPB  392      // NPIX / 128 pixels per histogram/scatter block
#define ROWQ (CF / 4) // 1056 float4 per pixfeat row
#define SEGCAP 768    // smem idx cap per segment (mean 392, 12+ sigma headroom)

// ---------------- scratch (static device memory only) ----------------------
__device__ int   g_hist[NS];
__device__ int   g_off[NS + 1];
__device__ int   g_bh[NS * NS];        // per-block per-segment counts
__device__ int   g_bcls[NS * NS * 3];  // per-block per-segment class counts
__device__ int   g_bbase[NS * NS];     // per-block per-segment write bases
__device__ int   g_perm[NPIX];
__device__ int   g_lab[NS];
__device__ float g_feat[NS * CF];
__device__ float g_G[NS * NS];
__device__ float g_h1[NS * DH];
__device__ float g_h2[NS * DH];

// ---------------- K1: per-block histograms + class counts ------------------
__global__ void k_hist(const int* __restrict__ sp, const int* __restrict__ y) {
    __shared__ int sh[NS];
    __shared__ int sc[NS * 3];
    for (int i = threadIdx.x; i < NS; i += 256) sh[i] = 0;
    for (int i = threadIdx.x; i < NS * 3; i += 256) sc[i] = 0;
    __syncthreads();
    int b = blockIdx.x;
    int base = b * PPB;
    for (int t = threadIdx.x; t < PPB; t += 256) {
        int i = base + t;
        int s = sp[i];
        atomicAdd(&sh[s], 1);
        atomicAdd(&sc[s * 3 + y[i]], 1);
    }
    __syncthreads();
    for (int i = threadIdx.x; i < NS; i += 256) g_bh[b * NS + i] = sh[i];
    for (int i = threadIdx.x; i < NS * 3; i += 256) g_bcls[b * NS * 3 + i] = sc[i];
}

// ---------------- K2: parallel meta — offsets, bases, exact labels ---------
// 1 block, 1024 threads: thread (g,s), g = tid>>7 in [0,8), s = tid&127.
// Each thread covers 16 hist-blocks for its segment, counts cached in regs.
__global__ void __launch_bounds__(1024) k_meta() {
    __shared__ int p_tot[8][NS];
    __shared__ int p_c0[8][NS];
    __shared__ int p_c1[8][NS];
    __shared__ int p_c2[8][NS];
    __shared__ int tot_sh[NS];
    __shared__ int off_sh[NS];
    int t = threadIdx.x;
    int g = t >> 7, s = t & 127;

    int bhv[16];
    int acc = 0, c0 = 0, c1 = 0, c2 = 0;
    #pragma unroll
    for (int bb = 0; bb < 16; bb++) {
        int b = g * 16 + bb;
        bhv[bb] = g_bh[b * NS + s];
        acc += bhv[bb];
        c0 += g_bcls[b * NS * 3 + s * 3 + 0];
        c1 += g_bcls[b * NS * 3 + s * 3 + 1];
        c2 += g_bcls[b * NS * 3 + s * 3 + 2];
    }
    p_tot[g][s] = acc; p_c0[g][s] = c0; p_c1[g][s] = c1; p_c2[g][s] = c2;
    __syncthreads();

    if (g == 0) {
        int T = 0, C0 = 0, C1 = 0, C2 = 0;
        #pragma unroll
        for (int gg = 0; gg < 8; gg++) {
            T += p_tot[gg][s]; C0 += p_c0[gg][s];
            C1 += p_c1[gg][s]; C2 += p_c2[gg][s];
        }
        tot_sh[s] = T;
        g_hist[s] = T;
        int lab = (C1 > C0) ? ((C2 > C1) ? 2 : 1) : ((C2 > C0) ? 2 : 0);
        if (lab == 0) lab = (C2 > (T >> 1)) ? 2 : ((C1 >= 1) ? 1 : 0);
        g_lab[s] = lab;
    }
    __syncthreads();
    if (t == 0) {
        int a = 0;
        for (int i = 0; i < NS; i++) { off_sh[i] = a; g_off[i] = a; a += tot_sh[i]; }
        g_off[NS] = a;
    }
    __syncthreads();
    int base = off_sh[s];
    for (int gg = 0; gg < g; gg++) base += p_tot[gg][s];
    #pragma unroll
    for (int bb = 0; bb < 16; bb++) {
        g_bbase[(g * 16 + bb) * NS + s] = base;
        base += bhv[bb];
    }
}

// ---------------- K3: scatter + zero the atomic accumulators ---------------
__global__ void k_scatter(const int* __restrict__ sp) {
    __shared__ int cur[NS];
    int b = blockIdx.x;
    for (int i = threadIdx.x; i < NS; i += 256) cur[i] = g_bbase[b * NS + i];
    __syncthreads();
    int base = b * PPB;
    for (int t = threadIdx.x; t < PPB; t += 256) {
        int i = base + t;
        int s = sp[i];
        int p = atomicAdd(&cur[s], 1);
        g_perm[p] = i;
    }
    // zero h1/h2 (1024 floats = 256 float4 per block each) and G (32 f4/block)
    float4 z = make_float4(0.f, 0.f, 0.f, 0.f);
    ((float4*)g_h1)[b * 256 + threadIdx.x] = z;
    ((float4*)g_h2)[b * 256 + threadIdx.x] = z;
    if (threadIdx.x < 32) ((float4*)g_G)[b * 32 + threadIdx.x] = z;
}

// ---------------- K4: segment mean (profiled slot; 84% DRAM) ---------------
__global__ void __launch_bounds__(256) k_segsum(const float* __restrict__ pix) {
    int ct = blockIdx.x;
    int s  = blockIdx.y;
    int tx = threadIdx.x & 31;
    int ty = threadIdx.x >> 5;
    int beg = g_off[s], end = g_off[s + 1];
    int n = end - beg;

    __shared__ int sidx[SEGCAP];
    int cap = n < SEGCAP ? n : SEGCAP;
    for (int i = threadIdx.x; i < cap; i += 256) sidx[i] = g_perm[beg + i];
    __syncthreads();

    const float4* __restrict__ p4 = (const float4*)pix;
    int colq = ct * 32 + tx;

    float4 A0 = make_float4(0.f, 0.f, 0.f, 0.f);
    float4 A1 = make_float4(0.f, 0.f, 0.f, 0.f);
    float4 A2 = make_float4(0.f, 0.f, 0.f, 0.f);
    float4 A3 = make_float4(0.f, 0.f, 0.f, 0.f);

    int r = ty;
    for (; r + 56 < cap; r += 64) {
        float4 v0 = __ldcs(p4 + (size_t)sidx[r]      * ROWQ + colq);
        float4 v1 = __ldcs(p4 + (size_t)sidx[r +  8] * ROWQ + colq);
        float4 v2 = __ldcs(p4 + (size_t)sidx[r + 16] * ROWQ + colq);
        float4 v3 = __ldcs(p4 + (size_t)sidx[r + 24] * ROWQ + colq);
        float4 v4 = __ldcs(p4 + (size_t)sidx[r + 32] * ROWQ + colq);
        float4 v5 = __ldcs(p4 + (size_t)sidx[r + 40] * ROWQ + colq);
        float4 v6 = __ldcs(p4 + (size_t)sidx[r + 48] * ROWQ + colq);
        float4 v7 = __ldcs(p4 + (size_t)sidx[r + 56] * ROWQ + colq);
        A0.x += v0.x; A0.y += v0.y; A0.z += v0.z; A0.w += v0.w;
        A1.x += v1.x; A1.y += v1.y; A1.z += v1.z; A1.w += v1.w;
        A2.x += v2.x; A2.y += v2.y; A2.z += v2.z; A2.w += v2.w;
        A3.x += v3.x; A3.y += v3.y; A3.z += v3.z; A3.w += v3.w;
        A0.x += v4.x; A0.y += v4.y; A0.z += v4.z; A0.w += v4.w;
        A1.x += v5.x; A1.y += v5.y; A1.z += v5.z; A1.w += v5.w;
        A2.x += v6.x; A2.y += v6.y; A2.z += v6.z; A2.w += v6.w;
        A3.x += v7.x; A3.y += v7.y; A3.z += v7.z; A3.w += v7.w;
    }
    for (; r < cap; r += 8) {
        float4 v0 = __ldcs(p4 + (size_t)sidx[r] * ROWQ + colq);
        A0.x += v0.x; A0.y += v0.y; A0.z += v0.z; A0.w += v0.w;
    }
    for (int r2 = SEGCAP + ty; r2 < n; r2 += 8) {  // statistically impossible
        float4 v0 = __ldcs(p4 + (size_t)g_perm[beg + r2] * ROWQ + colq);
        A0.x += v0.x; A0.y += v0.y; A0.z += v0.z; A0.w += v0.w;
    }
    A0.x += A1.x + A2.x + A3.x;
    A0.y += A1.y + A2.y + A3.y;
    A0.z += A1.z + A2.z + A3.z;
    A0.w += A1.w + A2.w + A3.w;

    __shared__ float4 red[8][32];
    red[ty][tx] = A0;
    __syncthreads();
    if (ty == 0) {
        float4 t = red[0][tx];
        #pragma unroll
        for (int w = 1; w < 8; w++) {
            t.x += red[w][tx].x; t.y += red[w][tx].y;
            t.z += red[w][tx].z; t.w += red[w][tx].w;
        }
        float c = (float)max(n, 1);
        t.x /= c; t.y /= c; t.z /= c; t.w /= c;
        *(float4*)&g_feat[s * CF + colq * 4] = t;
    }
}

// ---------------- K5: Gram matrix G = feat @ feat^T (split-K, 66 blocks) ---
__global__ void k_gram() {
    __shared__ float As[64][129];
    int kc  = blockIdx.x;
    int tid = threadIdx.x;
    {
        int k  = tid & 63;
        int io = tid >> 6;
        #pragma unroll 8
        for (int p = 0; p < 32; p++) {
            int i = p * 4 + io;
            As[k][i] = g_feat[i * CF + kc * 64 + k];
        }
    }
    __syncthreads();
    int tx = tid & 15, ty = tid >> 4;
    float acc[8][8];
    #pragma unroll
    for (int m = 0; m < 8; m++)
        #pragma unroll
        for (int n = 0; n < 8; n++) acc[m][n] = 0.f;

    for (int kk = 0; kk < 64; kk++) {
        float a[8], b[8];
        #pragma unroll
        for (int m = 0; m < 8; m++) a[m] = As[kk][ty * 8 + m];
        #pragma unroll
        for (int n = 0; n < 8; n++) b[n] = As[kk][tx * 8 + n];
        #pragma unroll
        for (int m = 0; m < 8; m++)
            #pragma unroll
            for (int n = 0; n < 8; n++) acc[m][n] += a[m] * b[n];
    }
    #pragma unroll
    for (int m = 0; m < 8; m++)
        #pragma unroll
        for (int n = 0; n < 8; n++)
            atomicAdd(&g_G[(ty * 8 + m) * NS + tx * 8 + n], acc[m][n]);
}

// ---------------- K6/K7: MLP GEMMs; gemm1 hosts label propagation ----------
// L==1: g_h1 = g_feat @ w1        (K=4224, 33 chunks of 128; +labels column)
// L==2: g_h2 = relu(g_h1+b1) @ w2 (K=1024, 16 chunks of 64)
template <int L>
__global__ void k_mlp_gemm(const float* __restrict__ B,
                           const float* __restrict__ bias,
                           float* __restrict__ out_lab) {
    const int N = DH;
    int ntile = blockIdx.x;

    if (L == 1 && ntile == 16) {
        // ---- label propagation (G is complete; runs once) ----
        if (blockIdx.y != 0) return;
        __shared__ float nrm[NS];
        __shared__ int   labsh[NS];
        int i = threadIdx.x;
        if (i < NS) {
            labsh[i] = g_lab[i];
            nrm[i] = rsqrtf(g_G[i * NS + i]);
        }
        __syncthreads();
        if (i < NS) {
            float maxv = -__int_as_float(0x7f800000);
            int best = 0;
            float ni = nrm[i];
            for (int j = 0; j < NS; j++) {
                if (labsh[j] != 0) {
                    float a = g_G[i * NS + j] * ni * nrm[j];
                    if (a > maxv) { maxv = a; best = j; }
                }
            }
            int lab = labsh[i];
            if (lab == 0 && maxv > 0.8f) lab = labsh[best];
            out_lab[i] = (float)lab;
        }
        return;
    }

    const float* __restrict__ A = (L == 1) ? g_feat : g_h1;
    float* C = (L == 1) ? g_h1 : g_h2;
    const int K = (L == 1) ? CF : DH;
    const int KCHUNK = (L == 1) ? 128 : 64;

    __shared__ float As[16][132];
    __shared__ float Bs[16][68];
    int tid = threadIdx.x;
    int tx = tid & 15, ty = tid >> 4;
    int k0 = blockIdx.y * KCHUNK;

    float acc[8][4];
    #pragma unroll
    for (int m = 0; m < 8; m++)
        #pragma unroll
        for (int n = 0; n < 4; n++) acc[m][n] = 0.f;

    for (int kt = 0; kt < KCHUNK; kt += 16) {
        #pragma unroll
        for (int p = 0; p < 8; p++) {
            int r = ty + p * 16;
            int kg = k0 + kt + tx;
            float v = A[r * K + kg];
            if (L == 2) v = fmaxf(v + bias[kg], 0.f);
            As[tx][r] = v;
        }
        #pragma unroll
        for (int p = 0; p < 4; p++) {
            int k = p * 4 + (tid >> 6);
            int n = tid & 63;
            Bs[k][n] = B[(k0 + kt + k) * N + ntile * 64 + n];
        }
        __syncthreads();
        #pragma unroll
        for (int kk = 0; kk < 16; kk++) {
            float a[8], b[4];
            #pragma unroll
            for (int m = 0; m < 8; m++) a[m] = As[kk][ty * 8 + m];
            #pragma unroll
            for (int n = 0; n < 4; n++) b[n] = Bs[kk][tx * 4 + n];
            #pragma unroll
            for (int m = 0; m < 8; m++)
                #pragma unroll
                for (int n = 0; n < 4; n++) acc[m][n] += a[m] * b[n];
        }
        __syncthreads();
    }
    #pragma unroll
    for (int m = 0; m < 8; m++) {
        int r = ty * 8 + m;
        #pragma unroll
        for (int n = 0; n < 4; n++)
            atomicAdd(&C[r * N + ntile * 64 + tx * 4 + n], acc[m][n]);
    }
}

// ---------------- K8: fused h3 = relu(h2+b2)@w3, head, softmax -------------
// grid = 128 (one segment per block), block = 256 = 32 cols x 8 k-groups
__global__ void k_tail(const float* __restrict__ b2,
                       const float* __restrict__ w3,
                       const float* __restrict__ b3,
                       const float* __restrict__ wc,
                       const float* __restrict__ bc,
                       float* __restrict__ out_probs) {
    int i = blockIdx.x;
    int j = threadIdx.x & 31;
    int g = threadIdx.x >> 5;
    const float* __restrict__ h2r = g_h2 + i * DH;
    float a0 = 0.f, a1 = 0.f;
    int kbase = g * 128;
    #pragma unroll 4
    for (int kk = 0; kk < 128; kk += 2) {
        int k = kbase + kk;
        a0 += fmaxf(h2r[k] + b2[k], 0.f) * w3[k * 32 + j];
        a1 += fmaxf(h2r[k + 1] + b2[k + 1], 0.f) * w3[(k + 1) * 32 + j];
    }
    __shared__ float red[8][32];
    red[g][j] = a0 + a1;
    __syncthreads();
    if (threadIdx.x < 32) {
        float tot = red[0][j];
        #pragma unroll
        for (int gg = 1; gg < 8; gg++) tot += red[gg][j];
        float h = fmaxf(tot + b3[j], 0.f);
        float p0 = h * wc[j * 2 + 0];
        float p1 = h * wc[j * 2 + 1];
        #pragma unroll
        for (int o = 16; o > 0; o >>= 1) {
            p0 += __shfl_xor_sync(0xffffffff, p0, o);
            p1 += __shfl_xor_sync(0xffffffff, p1, o);
        }
        if (j == 0) {
            float l0 = p0 + bc[0], l1 = p1 + bc[1];
            float m = fmaxf(l0, l1);
            float e0 = expf(l0 - m), e1 = expf(l1 - m);
            float s = e0 + e1;
            out_probs[i * 2 + 0] = e0 / s;
            out_probs[i * 2 + 1] = e1 / s;
        }
    }
}

// ---------------- launch ----------------------------------------------------
extern "C" void kernel_launch(void* const* d_in, const int* in_sizes, int n_in,
                              void* d_out, int out_size) {
    const float* pixfeat = (const float*)d_in[0];
    const float* w1 = (const float*)d_in[1];
    const float* b1 = (const float*)d_in[2];
    const float* w2 = (const float*)d_in[3];
    const float* b2 = (const float*)d_in[4];
    const float* w3 = (const float*)d_in[5];
    const float* b3 = (const float*)d_in[6];
    const float* wc = (const float*)d_in[7];
    const float* bc = (const float*)d_in[8];
    const int*   sp = (const int*)d_in[9];
    const int*   yy = (const int*)d_in[10];
    float* out = (float*)d_out;  // [0,256): probs, [256,384): lab

    k_hist<<<128, 256>>>(sp, yy);                  // 1
    k_meta<<<1, 1024>>>();                         // 2
    k_scatter<<<128, 256>>>(sp);                   // 3
    k_segsum<<<dim3(33, NS), 256>>>(pixfeat);      // 4 <- profiled slot
    k_gram<<<66, 256>>>();                         // 5
    k_mlp_gemm<1><<<dim3(17, 33), 256>>>(w1, nullptr, out + 256);  // 6 (+labels)
    k_mlp_gemm<2><<<dim3(16, 16), 256>>>(w2, b1, nullptr);         // 7
    k_tail<<<128, 256>>>(b2, w3, b3, wc, bc, out); // 8
}

// round 6
// speedup vs baseline: 1.7323x; 1.0199x over previous
#include <cuda_runtime.h>
#include <math.h>

#define NPIX 50176
#define CF   4224
#define NS   128
#define DH   1024
#define PPB  392      // NPIX / 128 pixels per prep block
#define ROWQ (CF / 4) // 1056 float4 per pixfeat row
#define SEGCAP 768    // smem idx cap per segment (mean 392, 12+ sigma headroom)

// ---------------- scratch (static device memory only) ----------------------
__device__ int   g_hist[NS];
__device__ int   g_off[NS + 1];
__device__ int   g_bh[NS * NS];        // per-block per-segment counts
__device__ int   g_bcls[NS * NS * 3];  // per-block per-segment class counts
__device__ int   g_perm[NPIX];
__device__ int   g_lab[NS];
__device__ float g_feat[NS * CF];
__device__ float g_G[NS * NS];
__device__ float g_h1[NS * DH];
__device__ float g_h2[NS * DH];
__device__ int   g_bar0;               // grid barrier counters (self-resetting)
__device__ int   g_bar1;

// ---------------- K1: fused hist + meta + scatter + zero -------------------
// 128 blocks x 256 threads, all co-resident (<= 148 SMs) -> spin barrier OK.
__global__ void __launch_bounds__(256) k_prep(const int* __restrict__ sp,
                                              const int* __restrict__ y) {
    __shared__ int sh[NS];
    __shared__ int sc[NS * 3];
    __shared__ int cur[NS];
    int b = blockIdx.x;
    int tid = threadIdx.x;

    // ---- phase A: per-block histogram + class counts ----
    for (int i = tid; i < NS; i += 256) sh[i] = 0;
    for (int i = tid; i < NS * 3; i += 256) sc[i] = 0;
    __syncthreads();
    int base = b * PPB;
    int s0 = sp[base + tid];
    int s1 = sp[base + 256 + ((tid < PPB - 256) ? tid : 0)];
    int y0 = y[base + tid];
    int y1 = y[base + 256 + ((tid < PPB - 256) ? tid : 0)];
    atomicAdd(&sh[s0], 1);
    atomicAdd(&sc[s0 * 3 + y0], 1);
    if (tid < PPB - 256) {
        atomicAdd(&sh[s1], 1);
        atomicAdd(&sc[s1 * 3 + y1], 1);
    }
    __syncthreads();
    for (int i = tid; i < NS; i += 256) g_bh[b * NS + i] = sh[i];
    for (int i = tid; i < NS * 3; i += 256) g_bcls[b * NS * 3 + i] = sc[i];

    // zero the atomic accumulators while we're here
    float4 z = make_float4(0.f, 0.f, 0.f, 0.f);
    ((float4*)g_h1)[b * 256 + tid] = z;
    ((float4*)g_h2)[b * 256 + tid] = z;
    if (tid < 32) ((float4*)g_G)[b * 32 + tid] = z;

    // ---- grid barrier 0 ----
    __threadfence();
    __syncthreads();
    if (tid == 0) {
        atomicAdd(&g_bar0, 1);
        while (*(volatile int*)&g_bar0 < NS) { }
    }
    __syncthreads();

    // ---- phase B: every block computes offsets + its own scatter bases ----
    __shared__ int off_sh[NS];
    __shared__ int tot_sh[NS];
    __shared__ int pre_sh[NS];   // sum over blocks b' < b
    if (tid < NS) {
        int s = tid;
        int tot = 0, pre = 0;
        for (int bb = 0; bb < NS; bb++) {
            int v = g_bh[bb * NS + s];
            if (bb < b) pre += v;
            tot += v;
        }
        tot_sh[s] = tot;
        pre_sh[s] = pre;
        if (b == 0) {
            g_hist[s] = tot;
            int c0 = 0, c1 = 0, c2 = 0;
            for (int bb = 0; bb < NS; bb++) {
                c0 += g_bcls[bb * NS * 3 + s * 3 + 0];
                c1 += g_bcls[bb * NS * 3 + s * 3 + 1];
                c2 += g_bcls[bb * NS * 3 + s * 3 + 2];
            }
            int lab = (c1 > c0) ? ((c2 > c1) ? 2 : 1) : ((c2 > c0) ? 2 : 0);
            if (lab == 0) lab = (c2 > (tot >> 1)) ? 2 : ((c1 >= 1) ? 1 : 0);
            g_lab[s] = lab;
        }
    }
    __syncthreads();
    if (tid == 0) {
        int a = 0;
        for (int i = 0; i < NS; i++) { off_sh[i] = a; a += tot_sh[i]; }
        if (b == 0) {
            for (int i = 0; i < NS; i++) g_off[i] = off_sh[i];
            g_off[NS] = a;
        }
    }
    __syncthreads();
    if (tid < NS) cur[tid] = off_sh[tid] + pre_sh[tid];
    __syncthreads();

    // ---- phase C: scatter ----
    {
        int p = atomicAdd(&cur[s0], 1);
        g_perm[p] = base + tid;
        if (tid < PPB - 256) {
            int q = atomicAdd(&cur[s1], 1);
            g_perm[q] = base + 256 + tid;
        }
    }

    // ---- barrier 1: arrive-only; last block resets counters for replay ----
    __threadfence();
    __syncthreads();
    if (tid == 0) {
        int v = atomicAdd(&g_bar1, 1);
        if (v == NS - 1) { g_bar0 = 0; g_bar1 = 0; }
    }
}

// ---------------- K2: segment mean (profiled slot; ~84% DRAM) --------------
__global__ void __launch_bounds__(256) k_segsum(const float* __restrict__ pix) {
    int ct = blockIdx.x;
    int s  = blockIdx.y;
    int tx = threadIdx.x & 31;
    int ty = threadIdx.x >> 5;
    int beg = g_off[s], end = g_off[s + 1];
    int n = end - beg;

    __shared__ int sidx[SEGCAP];
    int cap = n < SEGCAP ? n : SEGCAP;
    for (int i = threadIdx.x; i < cap; i += 256) sidx[i] = g_perm[beg + i];
    __syncthreads();

    const float4* __restrict__ p4 = (const float4*)pix;
    int colq = ct * 32 + tx;

    float4 A0 = make_float4(0.f, 0.f, 0.f, 0.f);
    float4 A1 = make_float4(0.f, 0.f, 0.f, 0.f);
    float4 A2 = make_float4(0.f, 0.f, 0.f, 0.f);
    float4 A3 = make_float4(0.f, 0.f, 0.f, 0.f);

    int r = ty;
    for (; r + 56 < cap; r += 64) {
        float4 v0 = __ldcs(p4 + (size_t)sidx[r]      * ROWQ + colq);
        float4 v1 = __ldcs(p4 + (size_t)sidx[r +  8] * ROWQ + colq);
        float4 v2 = __ldcs(p4 + (size_t)sidx[r + 16] * ROWQ + colq);
        float4 v3 = __ldcs(p4 + (size_t)sidx[r + 24] * ROWQ + colq);
        float4 v4 = __ldcs(p4 + (size_t)sidx[r + 32] * ROWQ + colq);
        float4 v5 = __ldcs(p4 + (size_t)sidx[r + 40] * ROWQ + colq);
        float4 v6 = __ldcs(p4 + (size_t)sidx[r + 48] * ROWQ + colq);
        float4 v7 = __ldcs(p4 + (size_t)sidx[r + 56] * ROWQ + colq);
        A0.x += v0.x; A0.y += v0.y; A0.z += v0.z; A0.w += v0.w;
        A1.x += v1.x; A1.y += v1.y; A1.z += v1.z; A1.w += v1.w;
        A2.x += v2.x; A2.y += v2.y; A2.z += v2.z; A2.w += v2.w;
        A3.x += v3.x; A3.y += v3.y; A3.z += v3.z; A3.w += v3.w;
        A0.x += v4.x; A0.y += v4.y; A0.z += v4.z; A0.w += v4.w;
        A1.x += v5.x; A1.y += v5.y; A1.z += v5.z; A1.w += v5.w;
        A2.x += v6.x; A2.y += v6.y; A2.z += v6.z; A2.w += v6.w;
        A3.x += v7.x; A3.y += v7.y; A3.z += v7.z; A3.w += v7.w;
    }
    for (; r < cap; r += 8) {
        float4 v0 = __ldcs(p4 + (size_t)sidx[r] * ROWQ + colq);
        A0.x += v0.x; A0.y += v0.y; A0.z += v0.z; A0.w += v0.w;
    }
    for (int r2 = SEGCAP + ty; r2 < n; r2 += 8) {  // statistically impossible
        float4 v0 = __ldcs(p4 + (size_t)g_perm[beg + r2] * ROWQ + colq);
        A0.x += v0.x; A0.y += v0.y; A0.z += v0.z; A0.w += v0.w;
    }
    A0.x += A1.x + A2.x + A3.x;
    A0.y += A1.y + A2.y + A3.y;
    A0.z += A1.z + A2.z + A3.z;
    A0.w += A1.w + A2.w + A3.w;

    __shared__ float4 red[8][32];
    red[ty][tx] = A0;
    __syncthreads();
    if (ty == 0) {
        float4 t = red[0][tx];
        #pragma unroll
        for (int w = 1; w < 8; w++) {
            t.x += red[w][tx].x; t.y += red[w][tx].y;
            t.z += red[w][tx].z; t.w += red[w][tx].w;
        }
        float c = (float)max(n, 1);
        t.x /= c; t.y /= c; t.z /= c; t.w /= c;
        *(float4*)&g_feat[s * CF + colq * 4] = t;
    }
}

// ---------------- K3: gemm1 (528 blocks) + gram (66 blocks), one launch ----
__global__ void k_gemm1_gram(const float* __restrict__ B /* w1 */) {
    int blk = blockIdx.x;
    int tid = threadIdx.x;

    if (blk >= 528) {
        // ---- gram: G += feat_chunk @ feat_chunk^T ----
        __shared__ float As[64][129];
        int kc = blk - 528;  // 66 chunks of 64 along CF
        {
            int k  = tid & 63;
            int io = tid >> 6;
            #pragma unroll 8
            for (int p = 0; p < 32; p++) {
                int i = p * 4 + io;
                As[k][i] = g_feat[i * CF + kc * 64 + k];
            }
        }
        __syncthreads();
        int tx = tid & 15, ty = tid >> 4;
        float acc[8][8];
        #pragma unroll
        for (int m = 0; m < 8; m++)
            #pragma unroll
            for (int n = 0; n < 8; n++) acc[m][n] = 0.f;
        for (int kk = 0; kk < 64; kk++) {
            float a[8], b[8];
            #pragma unroll
            for (int m = 0; m < 8; m++) a[m] = As[kk][ty * 8 + m];
            #pragma unroll
            for (int n = 0; n < 8; n++) b[n] = As[kk][tx * 8 + n];
            #pragma unroll
            for (int m = 0; m < 8; m++)
                #pragma unroll
                for (int n = 0; n < 8; n++) acc[m][n] += a[m] * b[n];
        }
        #pragma unroll
        for (int m = 0; m < 8; m++)
            #pragma unroll
            for (int n = 0; n < 8; n++)
                atomicAdd(&g_G[(ty * 8 + m) * NS + tx * 8 + n], acc[m][n]);
        return;
    }

    // ---- gemm1: h1 += feat @ w1, split-K (ntile = blk&15, kchunk = blk>>4)
    const int KCHUNK = 128;
    int ntile = blk & 15;
    int k0 = (blk >> 4) * KCHUNK;

    __shared__ float As[16][132];
    __shared__ float Bs[16][68];
    int tx = tid & 15, ty = tid >> 4;

    float acc[8][4];
    #pragma unroll
    for (int m = 0; m < 8; m++)
        #pragma unroll
        for (int n = 0; n < 4; n++) acc[m][n] = 0.f;

    for (int kt = 0; kt < KCHUNK; kt += 16) {
        #pragma unroll
        for (int p = 0; p < 8; p++) {
            int r = ty + p * 16;
            As[tx][r] = g_feat[r * CF + k0 + kt + tx];
        }
        #pragma unroll
        for (int p = 0; p < 4; p++) {
            int k = p * 4 + (tid >> 6);
            int n = tid & 63;
            Bs[k][n] = B[(k0 + kt + k) * DH + ntile * 64 + n];
        }
        __syncthreads();
        #pragma unroll
        for (int kk = 0; kk < 16; kk++) {
            float a[8], b[4];
            #pragma unroll
            for (int m = 0; m < 8; m++) a[m] = As[kk][ty * 8 + m];
            #pragma unroll
            for (int n = 0; n < 4; n++) b[n] = Bs[kk][tx * 4 + n];
            #pragma unroll
            for (int m = 0; m < 8; m++)
                #pragma unroll
                for (int n = 0; n < 4; n++) acc[m][n] += a[m] * b[n];
        }
        __syncthreads();
    }
    #pragma unroll
    for (int m = 0; m < 8; m++) {
        int r = ty * 8 + m;
        #pragma unroll
        for (int n = 0; n < 4; n++)
            atomicAdd(&g_h1[r * DH + ntile * 64 + tx * 4 + n], acc[m][n]);
    }
}

// ---------------- K4: gemm2 (256 blocks) + label propagation (1 block) -----
__global__ void k_gemm2_labels(const float* __restrict__ B /* w2 */,
                               const float* __restrict__ bias /* b1 */,
                               float* __restrict__ out_lab) {
    int blk = blockIdx.x;
    int tid = threadIdx.x;

    if (blk >= 256) {
        // ---- label propagation (G complete after previous launch) ----
        __shared__ float nrm[NS];
        __shared__ int   labsh[NS];
        int i = tid;
        if (i < NS) {
            labsh[i] = g_lab[i];
            nrm[i] = rsqrtf(g_G[i * NS + i]);
        }
        __syncthreads();
        if (i < NS) {
            float maxv = -__int_as_float(0x7f800000);
            int best = 0;
            float ni = nrm[i];
            for (int j = 0; j < NS; j++) {
                if (labsh[j] != 0) {
                    float a = g_G[i * NS + j] * ni * nrm[j];
                    if (a > maxv) { maxv = a; best = j; }
                }
            }
            int lab = labsh[i];
            if (lab == 0 && maxv > 0.8f) lab = labsh[best];
            out_lab[i] = (float)lab;
        }
        return;
    }

    const int KCHUNK = 64;
    int ntile = blk & 15;
    int k0 = (blk >> 4) * KCHUNK;

    __shared__ float As[16][132];
    __shared__ float Bs[16][68];
    int tx = tid & 15, ty = tid >> 4;

    float acc[8][4];
    #pragma unroll
    for (int m = 0; m < 8; m++)
        #pragma unroll
        for (int n = 0; n < 4; n++) acc[m][n] = 0.f;

    for (int kt = 0; kt < KCHUNK; kt += 16) {
        #pragma unroll
        for (int p = 0; p < 8; p++) {
            int r = ty + p * 16;
            int kg = k0 + kt + tx;
            As[tx][r] = fmaxf(g_h1[r * DH + kg] + bias[kg], 0.f);
        }
        #pragma unroll
        for (int p = 0; p < 4; p++) {
            int k = p * 4 + (tid >> 6);
            int n = tid & 63;
            Bs[k][n] = B[(k0 + kt + k) * DH + ntile * 64 + n];
        }
        __syncthreads();
        #pragma unroll
        for (int kk = 0; kk < 16; kk++) {
            float a[8], b[4];
            #pragma unroll
            for (int m = 0; m < 8; m++) a[m] = As[kk][ty * 8 + m];
            #pragma unroll
            for (int n = 0; n < 4; n++) b[n] = Bs[kk][tx * 4 + n];
            #pragma unroll
            for (int m = 0; m < 8; m++)
                #pragma unroll
                for (int n = 0; n < 4; n++) acc[m][n] += a[m] * b[n];
        }
        __syncthreads();
    }
    #pragma unroll
    for (int m = 0; m < 8; m++) {
        int r = ty * 8 + m;
        #pragma unroll
        for (int n = 0; n < 4; n++)
            atomicAdd(&g_h2[r * DH + ntile * 64 + tx * 4 + n], acc[m][n]);
    }
}

// ---------------- K5: fused h3 = relu(h2+b2)@w3, head, softmax -------------
__global__ void k_tail(const float* __restrict__ b2,
                       const float* __restrict__ w3,
                       const float* __restrict__ b3,
                       const float* __restrict__ wc,
                       const float* __restrict__ bc,
                       float* __restrict__ out_probs) {
    int i = blockIdx.x;
    int j = threadIdx.x & 31;
    int g = threadIdx.x >> 5;
    const float* __restrict__ h2r = g_h2 + i * DH;
    float a0 = 0.f, a1 = 0.f;
    int kbase = g * 128;
    #pragma unroll 4
    for (int kk = 0; kk < 128; kk += 2) {
        int k = kbase + kk;
        a0 += fmaxf(h2r[k] + b2[k], 0.f) * w3[k * 32 + j];
        a1 += fmaxf(h2r[k + 1] + b2[k + 1], 0.f) * w3[(k + 1) * 32 + j];
    }
    __shared__ float red[8][32];
    red[g][j] = a0 + a1;
    __syncthreads();
    if (threadIdx.x < 32) {
        float tot = red[0][j];
        #pragma unroll
        for (int gg = 1; gg < 8; gg++) tot += red[gg][j];
        float h = fmaxf(tot + b3[j], 0.f);
        float p0 = h * wc[j * 2 + 0];
        float p1 = h * wc[j * 2 + 1];
        #pragma unroll
        for (int o = 16; o > 0; o >>= 1) {
            p0 += __shfl_xor_sync(0xffffffff, p0, o);
            p1 += __shfl_xor_sync(0xffffffff, p1, o);
        }
        if (j == 0) {
            float l0 = p0 + bc[0], l1 = p1 + bc[1];
            float m = fmaxf(l0, l1);
            float e0 = expf(l0 - m), e1 = expf(l1 - m);
            float s = e0 + e1;
            out_probs[i * 2 + 0] = e0 / s;
            out_probs[i * 2 + 1] = e1 / s;
        }
    }
}

// ---------------- launch ----------------------------------------------------
extern "C" void kernel_launch(void* const* d_in, const int* in_sizes, int n_in,
                              void* d_out, int out_size) {
    const float* pixfeat = (const float*)d_in[0];
    const float* w1 = (const float*)d_in[1];
    const float* b1 = (const float*)d_in[2];
    const float* w2 = (const float*)d_in[3];
    const float* b2 = (const float*)d_in[4];
    const float* w3 = (const float*)d_in[5];
    const float* b3 = (const float*)d_in[6];
    const float* wc = (const float*)d_in[7];
    const float* bc = (const float*)d_in[8];
    const int*   sp = (const int*)d_in[9];
    const int*   yy = (const int*)d_in[10];
    float* out = (float*)d_out;  // [0,256): probs, [256,384): lab

    k_prep<<<NS, 256>>>(sp, yy);                          // 1 (hist+meta+scatter)
    k_segsum<<<dim3(33, NS), 256>>>(pixfeat);             // 2
    k_gemm1_gram<<<594, 256>>>(w1);                       // 3 (gemm1 + gram)
    k_gemm2_labels<<<257, 256>>>(w2, b1, out + 256);      // 4 (gemm2 + labels)
    k_tail<<<128, 256>>>(b2, w3, b3, wc, bc, out);        // 5
}